// round 2
// baseline (speedup 1.0000x reference)
#include <cuda_runtime.h>

#define NN    50000
#define EE    800000
#define ETOT  (EE + NN)
#define FIN   128
#define H1DIM 128   // HEADS*HID
#define NHEAD 8
#define CLS   40
#define NEG   0.2f

// ---------------- device scratch (static, allocation-free) ----------------
__device__ float g_h1[(size_t)NN * H1DIM];    // layer-1 pre-aggregation features
__device__ float g_hact[(size_t)NN * H1DIM];  // layer-1 output after bias+ELU
__device__ float g_e1s[NN * NHEAD];
__device__ float g_e1d[NN * NHEAD];
__device__ float g_h2[(size_t)NN * CLS];
__device__ float g_e2s[NN];
__device__ float g_e2d[NN];
__device__ int   g_rowptr[NN + 1];
__device__ int   g_counts[NN];
__device__ int   g_fill[NN];
__device__ int   g_srcs[ETOT];     // CSR-ordered sources
__device__ int   g_srcE[ETOT];     // normalized edge list (COO)
__device__ int   g_dstE[ETOT];
__device__ int   g_is64;

// ---------------- edge dtype detection + normalization ----------------
// JAX under default config silently downcasts int64 -> int32; handle both.
__global__ void detect_kernel(const void* ei) {
    const long long* e64 = (const long long*)ei;
    int ok = 1;
    for (int i = 0; i < 1024; i++) {
        long long v = e64[i];
        if (v < 0 || v >= NN) { ok = 0; break; }
    }
    g_is64 = ok;
}

__global__ void convert_kernel(const void* ei) {
    int i = blockIdx.x * blockDim.x + threadIdx.x;
    if (i >= ETOT) return;
    int s, d;
    if (i >= EE) {
        s = d = i - EE;                      // self-loops appended
    } else if (g_is64) {
        const long long* e = (const long long*)ei;
        s = (int)e[i]; d = (int)e[EE + i];
    } else {
        const int* e = (const int*)ei;
        s = e[i]; d = e[EE + i];
    }
    g_srcE[i] = s; g_dstE[i] = d;
}

// ---------------- CSR build ----------------
__global__ void zero_kernel() {
    int i = blockIdx.x * blockDim.x + threadIdx.x;
    if (i < NN) { g_counts[i] = 0; g_fill[i] = 0; }
}

__global__ void hist_kernel() {
    int i = blockIdx.x * blockDim.x + threadIdx.x;
    if (i >= ETOT) return;
    atomicAdd(&g_counts[g_dstE[i]], 1);
}

__global__ void scan_kernel() {
    __shared__ int sh[1024];
    __shared__ int carry;
    int tid = threadIdx.x;
    if (tid == 0) { carry = 0; g_rowptr[0] = 0; }
    __syncthreads();
    for (int base = 0; base < NN; base += 1024) {
        int v = (base + tid < NN) ? g_counts[base + tid] : 0;
        sh[tid] = v;
        __syncthreads();
        for (int off = 1; off < 1024; off <<= 1) {
            int t = (tid >= off) ? sh[tid - off] : 0;
            __syncthreads();
            sh[tid] += t;
            __syncthreads();
        }
        int c = carry;
        if (base + tid < NN) g_rowptr[base + tid + 1] = c + sh[tid];
        __syncthreads();
        if (tid == 0) carry = c + sh[1023];
        __syncthreads();
    }
}

__global__ void scatter_kernel() {
    int i = blockIdx.x * blockDim.x + threadIdx.x;
    if (i >= ETOT) return;
    int d = g_dstE[i];
    int pos = g_rowptr[d] + atomicAdd(&g_fill[d], 1);
    g_srcs[pos] = g_srcE[i];
}

// ---------------- GEMM1: h1 = x @ W1, fused e_src1/e_dst1 ----------------
// block = 128 threads (one per output col), 4 rows per block.
__global__ void gemm1_kernel(const float* __restrict__ x,
                             const float* __restrict__ W1,
                             const float* __restrict__ as1,
                             const float* __restrict__ ad1) {
    const int t = threadIdx.x;           // output column 0..127
    const int row0 = blockIdx.x * 4;     // NN % 4 == 0
    __shared__ float xt[FIN * 4];        // transposed: xt[k*4 + r]

#pragma unroll
    for (int r = 0; r < 4; r++)
        xt[t * 4 + r] = x[(size_t)(row0 + r) * FIN + t];
    __syncthreads();

    float a0 = 0.f, a1 = 0.f, a2 = 0.f, a3 = 0.f;
#pragma unroll 8
    for (int k = 0; k < FIN; k++) {
        float w = __ldg(&W1[k * H1DIM + t]);
        float4 xv = *(const float4*)&xt[k * 4];
        a0 = fmaf(w, xv.x, a0);
        a1 = fmaf(w, xv.y, a1);
        a2 = fmaf(w, xv.z, a2);
        a3 = fmaf(w, xv.w, a3);
    }

    float asv = __ldg(&as1[t]), adv = __ldg(&ad1[t]);
    float accs[4] = {a0, a1, a2, a3};
#pragma unroll
    for (int r = 0; r < 4; r++) {
        g_h1[(size_t)(row0 + r) * H1DIM + t] = accs[r];
        float ps = accs[r] * asv;
        float pd = accs[r] * adv;
#pragma unroll
        for (int off = 8; off > 0; off >>= 1) {
            ps += __shfl_down_sync(0xffffffffu, ps, off, 16);
            pd += __shfl_down_sync(0xffffffffu, pd, off, 16);
        }
        if ((t & 15) == 0) {
            g_e1s[(row0 + r) * NHEAD + (t >> 4)] = ps;
            g_e1d[(row0 + r) * NHEAD + (t >> 4)] = pd;
        }
    }
}

// ---------------- layer-1 aggregation: warp per dst node ----------------
__global__ void agg1_kernel(const float* __restrict__ b1) {
    int gw = (blockIdx.x * blockDim.x + threadIdx.x) >> 5;
    int lane = threadIdx.x & 31;
    if (gw >= NN) return;
    const int node = gw;
    const int beg = g_rowptr[node];
    const int end = g_rowptr[node + 1];

    float ed[8];
    {
        const float4* pd = (const float4*)(g_e1d + node * NHEAD);
        float4 d0 = pd[0], d1 = pd[1];
        ed[0] = d0.x; ed[1] = d0.y; ed[2] = d0.z; ed[3] = d0.w;
        ed[4] = d1.x; ed[5] = d1.y; ed[6] = d1.z; ed[7] = d1.w;
    }

    // pass 1: per-head max over incoming edges (lanes stride edges)
    float m[8];
#pragma unroll
    for (int h = 0; h < 8; h++) m[h] = -1e30f;
    for (int i = beg + lane; i < end; i += 32) {
        int s = g_srcs[i];
        const float4* ps = (const float4*)(g_e1s + s * NHEAD);
        float4 s0 = ps[0], s1 = ps[1];
        float ev[8] = {s0.x, s0.y, s0.z, s0.w, s1.x, s1.y, s1.z, s1.w};
#pragma unroll
        for (int h = 0; h < 8; h++) {
            float a = ev[h] + ed[h];
            a = a > 0.f ? a : NEG * a;
            m[h] = fmaxf(m[h], a);
        }
    }
#pragma unroll
    for (int off = 16; off > 0; off >>= 1)
#pragma unroll
        for (int h = 0; h < 8; h++)
            m[h] = fmaxf(m[h], __shfl_xor_sync(0xffffffffu, m[h], off));

    // pass 2: 4 edges/iter; each lane computes exp for one (edge, head)
    const int eh = lane & 7;       // head this lane computes w for
    const int sub = lane >> 3;     // which of the 4 edges
    const int myhead = lane >> 2;  // head owning this lane's 4 channels
    // select m/ed without dynamic register indexing (avoid local-mem spill)
    float mh = m[0], edh = ed[0];
#pragma unroll
    for (int h = 1; h < 8; h++) {
        mh = (eh == h) ? m[h] : mh;
        edh = (eh == h) ? ed[h] : edh;
    }

    float acc0 = 0.f, acc1 = 0.f, acc2 = 0.f, acc3 = 0.f, ssum = 0.f;
    for (int i = beg; i < end; i += 4) {
        int ei = i + sub;
        int s = 0;
        float w = 0.f;
        if (ei < end) {
            s = g_srcs[ei];
            float a = g_e1s[s * NHEAD + eh] + edh;
            a = a > 0.f ? a : NEG * a;
            w = __expf(a - mh);
        }
#pragma unroll
        for (int j = 0; j < 4; j++) {
            float wj = __shfl_sync(0xffffffffu, w, (j << 3) + myhead);
            int   sj = __shfl_sync(0xffffffffu, s, j << 3);
            if (i + j < end) {
                const float4 hv = *(const float4*)(g_h1 + (size_t)sj * H1DIM + lane * 4);
                acc0 = fmaf(wj, hv.x, acc0);
                acc1 = fmaf(wj, hv.y, acc1);
                acc2 = fmaf(wj, hv.z, acc2);
                acc3 = fmaf(wj, hv.w, acc3);
                ssum += wj;
            }
        }
    }

    float inv = 1.f / (ssum + 1e-16f);
    float4 bv = *(const float4*)(b1 + lane * 4);
    float v0 = acc0 * inv + bv.x;
    float v1 = acc1 * inv + bv.y;
    float v2 = acc2 * inv + bv.z;
    float v3 = acc3 * inv + bv.w;
    // ELU
    v0 = v0 > 0.f ? v0 : (__expf(v0) - 1.f);
    v1 = v1 > 0.f ? v1 : (__expf(v1) - 1.f);
    v2 = v2 > 0.f ? v2 : (__expf(v2) - 1.f);
    v3 = v3 > 0.f ? v3 : (__expf(v3) - 1.f);
    float4 outv = make_float4(v0, v1, v2, v3);
    *(float4*)(g_hact + (size_t)node * H1DIM + lane * 4) = outv;
}

// ---------------- GEMM2: h2 = hact @ W2, fused e_src2/e_dst2 ----------------
// warp per row; W2 transposed into smem per block.
__global__ void gemm2_kernel(const float* __restrict__ W2,
                             const float* __restrict__ as2,
                             const float* __restrict__ ad2) {
    __shared__ float W2T[CLS * FIN];  // 20 KB
    int tid = threadIdx.x;
    for (int i = tid; i < CLS * FIN; i += blockDim.x) {
        int c = i >> 7, k = i & 127;
        W2T[i] = W2[k * CLS + c];
    }
    __syncthreads();

    int gw = blockIdx.x * (blockDim.x >> 5) + (tid >> 5);
    int lane = tid & 31;
    if (gw >= NN) return;
    const int row = gw;

    float4 xv = *(const float4*)(g_hact + (size_t)row * FIN + lane * 4);
    float es = 0.f, edv = 0.f, v0 = 0.f, v1 = 0.f;
#pragma unroll 4
    for (int c = 0; c < CLS; c++) {
        float4 wv = *(const float4*)&W2T[c * FIN + lane * 4];
        float p = xv.x * wv.x + xv.y * wv.y + xv.z * wv.z + xv.w * wv.w;
#pragma unroll
        for (int off = 16; off > 0; off >>= 1)
            p += __shfl_xor_sync(0xffffffffu, p, off);
        es  = fmaf(p, __ldg(&as2[c]), es);
        edv = fmaf(p, __ldg(&ad2[c]), edv);
        if ((c & 31) == lane) { if (c < 32) v0 = p; else v1 = p; }
    }
    g_h2[(size_t)row * CLS + lane] = v0;
    if (lane < 8) g_h2[(size_t)row * CLS + 32 + lane] = v1;
    if (lane == 0) { g_e2s[row] = es; g_e2d[row] = edv; }
}

// ---------------- layer-2 aggregation: warp per dst node ----------------
__global__ void agg2_kernel(const float* __restrict__ b2, float* __restrict__ out) {
    int gw = (blockIdx.x * blockDim.x + threadIdx.x) >> 5;
    int lane = threadIdx.x & 31;
    if (gw >= NN) return;
    const int node = gw;
    const int beg = g_rowptr[node];
    const int end = g_rowptr[node + 1];
    const float edn = g_e2d[node];

    float m = -1e30f;
    for (int i = beg + lane; i < end; i += 32) {
        float a = g_e2s[g_srcs[i]] + edn;
        a = a > 0.f ? a : NEG * a;
        m = fmaxf(m, a);
    }
#pragma unroll
    for (int off = 16; off > 0; off >>= 1)
        m = fmaxf(m, __shfl_xor_sync(0xffffffffu, m, off));

    float acc0 = 0.f, acc1 = 0.f, ss = 0.f;
    for (int i = beg; i < end; i += 32) {
        int ei = i + lane;
        int s = 0;
        float w = 0.f;
        if (ei < end) {
            s = g_srcs[ei];
            float a = g_e2s[s] + edn;
            a = a > 0.f ? a : NEG * a;
            w = __expf(a - m);
        }
        int cnt = min(32, end - i);
        for (int j = 0; j < cnt; j++) {
            float wj = __shfl_sync(0xffffffffu, w, j);
            int   sj = __shfl_sync(0xffffffffu, s, j);
            acc0 = fmaf(wj, g_h2[(size_t)sj * CLS + lane], acc0);
            if (lane < 8)
                acc1 = fmaf(wj, g_h2[(size_t)sj * CLS + 32 + lane], acc1);
            ss += wj;
        }
    }
    float inv = 1.f / (ss + 1e-16f);
    out[(size_t)node * CLS + lane] = acc0 * inv + __ldg(&b2[lane]);
    if (lane < 8)
        out[(size_t)node * CLS + 32 + lane] = acc1 * inv + __ldg(&b2[32 + lane]);
}

// ---------------- launch ----------------
extern "C" void kernel_launch(void* const* d_in, const int* in_sizes, int n_in,
                              void* d_out, int out_size) {
    const float* x   = (const float*)d_in[0];
    const void*  ei  = d_in[1];
    const float* W1  = (const float*)d_in[2];
    const float* as1 = (const float*)d_in[3];
    const float* ad1 = (const float*)d_in[4];
    const float* b1  = (const float*)d_in[5];
    const float* W2  = (const float*)d_in[6];
    const float* as2 = (const float*)d_in[7];
    const float* ad2 = (const float*)d_in[8];
    const float* b2  = (const float*)d_in[9];
    float* out = (float*)d_out;

    detect_kernel<<<1, 1>>>(ei);
    convert_kernel<<<(ETOT + 255) / 256, 256>>>(ei);
    zero_kernel<<<(NN + 255) / 256, 256>>>();
    gemm1_kernel<<<NN / 4, 128>>>(x, W1, as1, ad1);
    hist_kernel<<<(ETOT + 255) / 256, 256>>>();
    scan_kernel<<<1, 1024>>>();
    scatter_kernel<<<(ETOT + 255) / 256, 256>>>();
    agg1_kernel<<<(NN + 7) / 8, 256>>>(b1);
    gemm2_kernel<<<(NN + 7) / 8, 256>>>(W2, as2, ad2);
    agg2_kernel<<<(NN + 7) / 8, 256>>>(b2, out);
}